// round 15
// baseline (speedup 1.0000x reference)
#include <cuda_runtime.h>
#include <cuda_bf16.h>
#include <math.h>
#include <cstdint>

// Problem constants
constexpr int B_  = 2;
constexpr int S_  = 2048;
constexpr int D_  = 1024;
constexpr int H_  = 16;
constexpr int HD_ = 64;
constexpr int M_  = B_ * S_;       // 4096

// Scratch (device globals). Blocked layouts for single-bulk 8 KB tiles.
__device__ __nv_bfloat16 g_xh[M_ * D_];
__device__ __nv_bfloat16 g_xl[M_ * D_];
__device__ __nv_bfloat16 g_wh[4 * D_ * D_];
__device__ __nv_bfloat16 g_wl[4 * D_ * D_];
__device__ __nv_bfloat16 g_Qh[B_ * H_ * S_ * HD_];   // Q LINEAR [b,h,s,hd]
__device__ __nv_bfloat16 g_Ql[B_ * H_ * S_ * HD_];
__device__ __nv_bfloat16 g_Kh[B_ * H_ * S_ * HD_];   // K blocked
__device__ __nv_bfloat16 g_Kl[B_ * H_ * S_ * HD_];
__device__ __nv_bfloat16 g_Vth[B_ * H_ * HD_ * S_];  // V^T blocked
__device__ __nv_bfloat16 g_Vtl[B_ * H_ * HD_ * S_];

// ---------------------------------------------------------------------------
// Blocked-layout byte offsets
// ---------------------------------------------------------------------------
__device__ __forceinline__ size_t ablk_off(int row, int col) {
    const int r = row & 127;
    const int g = ((col >> 3) & 3) ^ ((r >> 1) & 3);
    return (((size_t)(row >> 7) * 32 + (col >> 5)) << 13) + r * 64 + g * 16 + (col & 7) * 2;
}
__device__ __forceinline__ size_t kblk_off(int bh, int s, int hd) {
    const int r = s & 63;
    const int g = (hd >> 3) ^ (r & 7);
    return (((size_t)bh * 32 + (s >> 6)) << 13) + r * 128 + g * 16 + (hd & 7) * 2;
}
__device__ __forceinline__ size_t vblk_off(int bh, int s, int hd) {
    const int r = hd;
    const int c = s & 63;
    const int g = (c >> 3) ^ (r & 7);
    return (((size_t)bh * 32 + (s >> 6)) << 13) + r * 128 + g * 16 + (c & 7) * 2;
}

// ---------------------------------------------------------------------------
// PTX helpers
// ---------------------------------------------------------------------------
__device__ __forceinline__ uint32_t smem_to_u32(const void* p) {
    uint32_t a;
    asm("{ .reg .u64 t; cvta.to.shared.u64 t, %1; cvt.u32.u64 %0, t; }"
        : "=r"(a) : "l"(p));
    return a;
}

__device__ __forceinline__ void ldsm_x4(uint32_t* r, uint32_t addr) {
    asm volatile("ldmatrix.sync.aligned.m8n8.x4.shared.b16 {%0,%1,%2,%3}, [%4];"
        : "=r"(r[0]), "=r"(r[1]), "=r"(r[2]), "=r"(r[3]) : "r"(addr));
}

__device__ __forceinline__ void mma_bf16(float* c, const uint32_t* a, const uint32_t* b) {
    asm volatile(
        "mma.sync.aligned.m16n8k16.row.col.f32.bf16.bf16.f32 "
        "{%0,%1,%2,%3}, {%4,%5,%6,%7}, {%8,%9}, {%0,%1,%2,%3};"
        : "+f"(c[0]), "+f"(c[1]), "+f"(c[2]), "+f"(c[3])
        : "r"(a[0]), "r"(a[1]), "r"(a[2]), "r"(a[3]),
          "r"(b[0]), "r"(b[1]));
}

#define MBARRIER_INIT(mbar, count) \
    asm volatile("mbarrier.init.shared.b64 [%0], %1;" \
        :: "r"((uint32_t)(mbar)), "r"((uint32_t)(count)) : "memory")

#define MBARRIER_ARRIVE(mbar) \
    asm volatile("mbarrier.arrive.shared.b64 _, [%0];" \
        :: "r"((uint32_t)(mbar)) : "memory")

#define MBARRIER_EXPECT_TX(mbar, tx_bytes) \
    asm volatile("mbarrier.arrive.expect_tx.shared.b64 _, [%0], %1;" \
        :: "r"((uint32_t)(mbar)), "r"((uint32_t)(tx_bytes)) : "memory")

#define MBARRIER_WAIT_PARITY(mbar_smem_addr, phase_parity) do { \
    uint32_t _mbar = (uint32_t)(mbar_smem_addr); \
    uint32_t _parity = (uint32_t)(phase_parity); \
    uint32_t _done; \
    asm volatile( \
        "{\n\t.reg .pred p;\n\t" \
        "mbarrier.try_wait.parity.acquire.cta.shared::cta.b64 p, [%1], %2;\n\t" \
        "selp.b32 %0, 1, 0, p;\n\t}" \
        : "=r"(_done) : "r"(_mbar), "r"(_parity) : "memory"); \
    if (!_done) { \
        asm volatile( \
            "{\n\t.reg .pred P1;\n\t" \
            "WAIT_LOOP_%=:\n\t" \
            "mbarrier.try_wait.parity.acquire.cta.shared::cta.b64 P1, [%0], %1, 0x989680;\n\t" \
            "@P1 bra.uni WAIT_DONE_%=;\n\t" \
            "bra.uni WAIT_LOOP_%=;\n\t" \
            "WAIT_DONE_%=:\n\t}" \
            :: "r"(_mbar), "r"(_parity) : "memory"); \
    } \
} while(0)

#define CP_BULK(dst, src, bytes, mbar) \
    asm volatile("cp.async.bulk.shared::cta.global.mbarrier::complete_tx::bytes [%0], [%1], %2, [%3];" \
        :: "r"((uint32_t)(dst)), "l"(src), "r"((uint32_t)(bytes)), "r"((uint32_t)(mbar)) : "memory")

// FMA-pipe exp2 (avoids the MUFU ceiling).
__device__ __forceinline__ float exp2p(float x) {
    x = fmaxf(x, -28.0f);
    float n = floorf(x);
    float f = x - n;
    float p = 1.54035304e-4f;
    p = fmaf(p, f, 1.33335581e-3f);
    p = fmaf(p, f, 9.61812911e-3f);
    p = fmaf(p, f, 5.55041087e-2f);
    p = fmaf(p, f, 2.40226507e-1f);
    p = fmaf(p, f, 6.93147181e-1f);
    p = fmaf(p, f, 1.0f);
    return __int_as_float(__float_as_int(p) + (((int)n) << 23));
}

__device__ __forceinline__ void split_bf16(float v, __nv_bfloat16& h, __nv_bfloat16& l) {
    h = __float2bfloat16(v);
    l = __float2bfloat16(v - __bfloat162float(h));
}

// ---------------------------------------------------------------------------
// One-shot converter: x -> g_xh/g_xl (blocked) ; Wq..Wo -> g_wh/g_wl (blocked)
// ---------------------------------------------------------------------------
__global__ void __launch_bounds__(256)
convert_all_kernel(const float* __restrict__ x,
                   const float* __restrict__ Wq, const float* __restrict__ Wk,
                   const float* __restrict__ Wv, const float* __restrict__ Wo)
{
    const int tid = threadIdx.x;
    const int blk = blockIdx.x;

    const float* src;
    __nv_bfloat16 *hi, *lo;
    int row;
    if (blk < 4096) {
        src = x + (size_t)blk * 1024; hi = g_xh; lo = g_xl; row = blk;
    } else {
        const int t = blk - 4096;
        const int w = t >> 10;
        const int lb = t & 1023;
        src = ((w == 0) ? Wq : (w == 1) ? Wk : (w == 2) ? Wv : Wo) + (size_t)lb * 1024;
        hi = g_wh; lo = g_wl; row = w * 1024 + lb;
    }

    const int col = tid * 4;
    float4 v = *(const float4*)(src + col);
    float f[4] = {v.x, v.y, v.z, v.w};
    __nv_bfloat16 h[4], l[4];
#pragma unroll
    for (int k = 0; k < 4; k++) split_bf16(f[k], h[k], l[k]);

    const size_t off = ablk_off(row, col);
    *(__nv_bfloat162*)((char*)hi + off)     = __halves2bfloat162(h[0], h[1]);
    *(__nv_bfloat162*)((char*)hi + off + 4) = __halves2bfloat162(h[2], h[3]);
    *(__nv_bfloat162*)((char*)lo + off)     = __halves2bfloat162(l[0], l[1]);
    *(__nv_bfloat162*)((char*)lo + off + 4) = __halves2bfloat162(l[2], l[3]);
}

// ---------------------------------------------------------------------------
// bf16x3 GEMM via mma.sync + TMA-bulk staging, warp-decoupled pipeline
// (unchanged from round 14, known-good).
// ---------------------------------------------------------------------------
constexpr int GSTAGE    = 32768;
constexpr int GEMM_SMEM = 3 * GSTAGE;

__global__ void __launch_bounds__(256, 2)
gemm_mma_kernel(const float* __restrict__ b0,
                const float* __restrict__ b1,
                const float* __restrict__ b2,
                float* __restrict__ dst,
                int wrow0)
{
    extern __shared__ __align__(1024) char smem[];
    __shared__ __align__(8) uint64_t mbar_st[6];      // full[3], empty[3]
    const uint32_t sb  = smem_to_u32(smem);
    const uint32_t mbF = smem_to_u32(&mbar_st[0]);
    const uint32_t mbE = smem_to_u32(&mbar_st[3]);
    const int tid = threadIdx.x;
    const int wid = tid >> 5;
    const int lid = tid & 31;
    const int wm  = wid & 3;
    const int wn  = wid >> 2;
    const int bm  = blockIdx.y * 128;
    const int bn  = blockIdx.x * 128;
    const int sel = bn >> 10;

    const float* bias = dst ? b0 : (sel == 0 ? b0 : sel == 1 ? b1 : b2);
    const int wt = (wrow0 + bn) >> 7;

    if (tid == 0) {
#pragma unroll
        for (int i = 0; i < 3; i++) {
            MBARRIER_INIT(mbF + i * 8, 1);
            MBARRIER_INIT(mbE + i * 8, 8);
        }
    }
    __syncthreads();

    auto issue = [&](int st) {
        const int b = st % 3;
        const uint32_t d  = sb + b * GSTAGE;
        const uint32_t mb = mbF + b * 8;
        MBARRIER_EXPECT_TX(mb, 32768);
        const size_t at = (((size_t)blockIdx.y * 32 + st) << 13);
        const size_t bt = (((size_t)wt * 32 + st) << 13);
        CP_BULK(d,         (const char*)g_xh + at, 8192, mb);
        CP_BULK(d + 8192,  (const char*)g_xl + at, 8192, mb);
        CP_BULK(d + 16384, (const char*)g_wh + bt, 8192, mb);
        CP_BULK(d + 24576, (const char*)g_wl + bt, 8192, mb);
    };
    if (tid == 0) { issue(0); issue(1); issue(2); }

    float c[2][8][4];
#pragma unroll
    for (int i = 0; i < 2; i++)
#pragma unroll
        for (int j = 0; j < 8; j++)
#pragma unroll
            for (int k = 0; k < 4; k++) c[i][j][k] = 0.f;

    const uint32_t a_r  = lid & 15;
    const uint32_t a_g0 = (lid >> 4) & 1;
    const uint32_t b_r  = ((lid >> 4) * 8) + (lid & 7);
    const uint32_t b_g0 = (lid >> 3) & 1;

    const int NCH = D_ / 32;
    for (int ch = 0; ch < NCH; ch++) {
        const int st = ch % 3;
        MBARRIER_WAIT_PARITY(mbF + st * 8, (ch / 3) & 1);

        const uint32_t sA_h = sb + st * GSTAGE;
        const uint32_t sA_l = sA_h + 8192;
        const uint32_t sB_h = sA_h + 16384;
        const uint32_t sB_l = sA_h + 24576;

        auto boff_of = [&](int kk, int np) -> uint32_t {
            const uint32_t br = wn * 64 + np * 16 + b_r;
            const uint32_t gb = (kk * 2 + b_g0) ^ ((br >> 1) & 3);
            return br * 64 + gb * 16;
        };

#pragma unroll
        for (int kk = 0; kk < 2; kk++) {
            uint32_t ah[2][4], al[2][4];
#pragma unroll
            for (int mt = 0; mt < 2; mt++) {
                const uint32_t ar = wm * 32 + mt * 16 + a_r;
                const uint32_t ga = (kk * 2 + a_g0) ^ ((ar >> 1) & 3);
                const uint32_t aoff = ar * 64 + ga * 16;
                ldsm_x4(ah[mt], sA_h + aoff);
                ldsm_x4(al[mt], sA_l + aoff);
            }
            uint32_t bh[2][4], bl[2][4];
            {
                const uint32_t o0 = boff_of(kk, 0);
                ldsm_x4(bh[0], sB_h + o0);
                ldsm_x4(bl[0], sB_l + o0);
            }
#pragma unroll
            for (int np = 0; np < 4; np++) {
                const int cur = np & 1;
                if (np < 3) {
                    const uint32_t on = boff_of(kk, np + 1);
                    ldsm_x4(bh[cur ^ 1], sB_h + on);
                    ldsm_x4(bl[cur ^ 1], sB_l + on);
                }
#pragma unroll
                for (int mt = 0; mt < 2; mt++) {
                    mma_bf16(c[mt][2*np],   ah[mt], bh[cur]);       // hh
                    mma_bf16(c[mt][2*np+1], ah[mt], bh[cur] + 2);
                    mma_bf16(c[mt][2*np],   ah[mt], bl[cur]);       // hl
                    mma_bf16(c[mt][2*np+1], ah[mt], bl[cur] + 2);
                    mma_bf16(c[mt][2*np],   al[mt], bh[cur]);       // lh
                    mma_bf16(c[mt][2*np+1], al[mt], bh[cur] + 2);
                }
            }
        }

        if (lid == 0) MBARRIER_ARRIVE(mbE + st * 8);
        if (tid == 0 && ch + 3 < NCH) {
            MBARRIER_WAIT_PARITY(mbE + st * 8, (ch / 3) & 1);
            issue(ch + 3);
        }
    }

    // ---- epilogue ------------------------------------------------------
#pragma unroll
    for (int mt = 0; mt < 2; mt++) {
#pragma unroll
        for (int nt = 0; nt < 8; nt++) {
            const int row0 = bm + wm * 32 + mt * 16 + (lid >> 2);
            const int row1 = row0 + 8;
            const int col  = bn + wn * 64 + nt * 8 + (lid & 3) * 2;
            const int colw = col & 1023;
            const float bx = __ldg(bias + colw);
            const float by = __ldg(bias + colw + 1);
            float v0 = c[mt][nt][0] + bx, v1 = c[mt][nt][1] + by;
            float v2 = c[mt][nt][2] + bx, v3 = c[mt][nt][3] + by;

            if (dst) {
                *(float2*)(dst + (size_t)row0 * D_ + col) = make_float2(v0, v1);
                *(float2*)(dst + (size_t)row1 * D_ + col) = make_float2(v2, v3);
            } else {
                const int h  = colw >> 6;
                const int hd = colw & 63;
                const int bb0 = row0 >> 11, ss0 = row0 & (S_ - 1);
                const int bb1 = row1 >> 11, ss1 = row1 & (S_ - 1);
                const int bhi0 = bb0 * H_ + h, bhi1 = bb1 * H_ + h;
                __nv_bfloat16 h0,l0,h1,l1,h2,l2,h3,l3;
                split_bf16(v0,h0,l0); split_bf16(v1,h1,l1);
                split_bf16(v2,h2,l2); split_bf16(v3,h3,l3);
                if (sel == 2) {
                    *(__nv_bfloat16*)((char*)g_Vth + vblk_off(bhi0, ss0, hd))     = h0;
                    *(__nv_bfloat16*)((char*)g_Vtl + vblk_off(bhi0, ss0, hd))     = l0;
                    *(__nv_bfloat16*)((char*)g_Vth + vblk_off(bhi0, ss0, hd + 1)) = h1;
                    *(__nv_bfloat16*)((char*)g_Vtl + vblk_off(bhi0, ss0, hd + 1)) = l1;
                    *(__nv_bfloat16*)((char*)g_Vth + vblk_off(bhi1, ss1, hd))     = h2;
                    *(__nv_bfloat16*)((char*)g_Vtl + vblk_off(bhi1, ss1, hd))     = l2;
                    *(__nv_bfloat16*)((char*)g_Vth + vblk_off(bhi1, ss1, hd + 1)) = h3;
                    *(__nv_bfloat16*)((char*)g_Vtl + vblk_off(bhi1, ss1, hd + 1)) = l3;
                } else if (sel == 1) {
                    const size_t o0 = kblk_off(bhi0, ss0, hd);
                    const size_t o1 = kblk_off(bhi1, ss1, hd);
                    *(__nv_bfloat162*)((char*)g_Kh + o0) = __halves2bfloat162(h0, h1);
                    *(__nv_bfloat162*)((char*)g_Kl + o0) = __halves2bfloat162(l0, l1);
                    *(__nv_bfloat162*)((char*)g_Kh + o1) = __halves2bfloat162(h2, h3);
                    *(__nv_bfloat162*)((char*)g_Kl + o1) = __halves2bfloat162(l2, l3);
                } else {
                    size_t i0 = (((size_t)bhi0 * S_) + ss0) * HD_ + hd;
                    size_t i1 = (((size_t)bhi1 * S_) + ss1) * HD_ + hd;
                    *(__nv_bfloat162*)(g_Qh + i0) = __halves2bfloat162(h0, h1);
                    *(__nv_bfloat162*)(g_Ql + i0) = __halves2bfloat162(l0, l1);
                    *(__nv_bfloat162*)(g_Qh + i1) = __halves2bfloat162(h2, h3);
                    *(__nv_bfloat162*)(g_Ql + i1) = __halves2bfloat162(l2, l3);
                }
            }
        }
    }
}

// ---------------------------------------------------------------------------
// Flash attention, FAT-WARP version: 4 warps (128 threads), each warp owns
// 32 query rows (mt = 0,1). Every K/V fragment load now feeds 12 MMAs
// instead of 6 -> smem LDSM traffic per CTA halves; tensor work unchanged.
// Static softmax; per-output-element op order unchanged -> bit-identical.
// ---------------------------------------------------------------------------
constexpr int FSTAGE     = 32768;
constexpr int FLASH_SMEM = 3 * FSTAGE;
constexpr float SCL2 = 0.18033688f;            // 0.125 * log2(e)

__global__ void __launch_bounds__(128, 2)
flash_mma_kernel()
{
    extern __shared__ __align__(1024) char fsm[];
    __shared__ __align__(8) uint64_t fmbar_st[6];     // full[3], empty[3]
    const uint32_t sb  = smem_to_u32(fsm);
    const uint32_t mbF = smem_to_u32(&fmbar_st[0]);
    const uint32_t mbE = smem_to_u32(&fmbar_st[3]);
    const int tid = threadIdx.x;
    const int wid = tid >> 5;                  // 0..3
    const int lid = tid & 31;
    const int bh  = blockIdx.y;
    const int q0  = blockIdx.x * 128;

    const size_t qk_base = (size_t)bh * S_ * HD_;
    const __nv_bfloat16* Qh = g_Qh + qk_base;
    const __nv_bfloat16* Ql = g_Ql + qk_base;
    const char* Khb = (const char*)g_Kh + ((size_t)bh * 32 << 13);
    const char* Klb = (const char*)g_Kl + ((size_t)bh * 32 << 13);
    const char* Vhb = (const char*)g_Vth + ((size_t)bh * 32 << 13);
    const char* Vlb = (const char*)g_Vtl + ((size_t)bh * 32 << 13);

    if (tid == 0) {
#pragma unroll
        for (int i = 0; i < 3; i++) {
            MBARRIER_INIT(mbF + i * 8, 1);
            MBARRIER_INIT(mbE + i * 8, 4);     // one arrive per warp
        }
    }
    __syncthreads();

    auto issue = [&](int t) {
        const int b = t % 3;
        const uint32_t d  = sb + b * FSTAGE;
        const uint32_t mb = mbF + b * 8;
        MBARRIER_EXPECT_TX(mb, 32768);
        const size_t toff = ((size_t)t << 13);
        CP_BULK(d,         Khb + toff, 8192, mb);
        CP_BULK(d + 8192,  Klb + toff, 8192, mb);
        CP_BULK(d + 16384, Vhb + toff, 8192, mb);
        CP_BULK(d + 24576, Vlb + toff, 8192, mb);
    };
    if (tid == 0) { issue(0); issue(1); issue(2); }

    // Q fragments straight from gmem: warp owns rows [wid*32, wid*32+32)
    uint32_t qfh[2][4][4], qfl[2][4][4];       // [mt][kk][reg]
    {
        const int g  = lid >> 2;
        const int tq = lid & 3;
#pragma unroll
        for (int mt = 0; mt < 2; mt++) {
            const int row0 = q0 + wid * 32 + mt * 16 + g;
#pragma unroll
            for (int kk = 0; kk < 4; kk++) {
                const int c0 = kk * 16 + 2 * tq;
                const size_t i00 = (size_t)row0 * HD_ + c0;
                const size_t i10 = i00 + 8 * HD_;
                qfh[mt][kk][0] = *(const uint32_t*)(Qh + i00);
                qfh[mt][kk][1] = *(const uint32_t*)(Qh + i10);
                qfh[mt][kk][2] = *(const uint32_t*)(Qh + i00 + 8);
                qfh[mt][kk][3] = *(const uint32_t*)(Qh + i10 + 8);
                qfl[mt][kk][0] = *(const uint32_t*)(Ql + i00);
                qfl[mt][kk][1] = *(const uint32_t*)(Ql + i10);
                qfl[mt][kk][2] = *(const uint32_t*)(Ql + i00 + 8);
                qfl[mt][kk][3] = *(const uint32_t*)(Ql + i10 + 8);
            }
        }
    }

    const uint32_t b_r  = ((lid >> 4) * 8) + (lid & 7);
    const uint32_t b_g0 = (lid >> 3) & 1;

    float o[2][8][4];                          // [mt][nt][reg]
#pragma unroll
    for (int m = 0; m < 2; m++)
#pragma unroll
        for (int i = 0; i < 8; i++)
#pragma unroll
            for (int j = 0; j < 4; j++) o[m][i][j] = 0.f;
    float lsum[2][2] = {{0.f, 0.f}, {0.f, 0.f}};   // [mt][half]

    const int NKV = S_ / 64;
    for (int t = 0; t < NKV; t++) {
        const int st = t % 3;
        MBARRIER_WAIT_PARITY(mbF + st * 8, (t / 3) & 1);

        const uint32_t sKh = sb + st * FSTAGE;
        const uint32_t sKl = sKh + 8192;
        const uint32_t sVh = sKh + 16384;
        const uint32_t sVl = sKh + 24576;

#pragma unroll
        for (int g = 0; g < 4; g++) {
            // ---- QK(g) for both mt: each K fragment feeds 12 MMAs ----------
            float cg[2][2][4];                 // [mt][half]
#pragma unroll
            for (int m = 0; m < 2; m++)
#pragma unroll
                for (int j = 0; j < 4; j++) { cg[m][0][j] = 0.f; cg[m][1][j] = 0.f; }

#pragma unroll
            for (int kk = 0; kk < 4; kk++) {
                uint32_t kfh[4], kfl[4];
                const uint32_t kr = g * 16 + b_r;
                const uint32_t gk = (kk * 2 + b_g0) ^ (kr & 7);
                const uint32_t koff = kr * 128 + gk * 16;
                ldsm_x4(kfh, sKh + koff);
                ldsm_x4(kfl, sKl + koff);
#pragma unroll
                for (int mt = 0; mt < 2; mt++) {
                    mma_bf16(cg[mt][0], qfh[mt][kk], kfh);        // hh
                    mma_bf16(cg[mt][1], qfh[mt][kk], kfh + 2);
                    mma_bf16(cg[mt][0], qfh[mt][kk], kfl);        // hl
                    mma_bf16(cg[mt][1], qfh[mt][kk], kfl + 2);
                    mma_bf16(cg[mt][0], qfl[mt][kk], kfh);        // lh
                    mma_bf16(cg[mt][1], qfl[mt][kk], kfh + 2);
                }
            }

            // ---- exp + row-sum partials + pack (both mt) --------------------
            uint32_t pfh[2][4], pfl[2][4];
#pragma unroll
            for (int mt = 0; mt < 2; mt++) {
#pragma unroll
                for (int hl = 0; hl < 2; hl++) {
                    cg[mt][hl][0] = exp2p(cg[mt][hl][0] * SCL2);
                    cg[mt][hl][1] = exp2p(cg[mt][hl][1] * SCL2);
                    cg[mt][hl][2] = exp2p(cg[mt][hl][2] * SCL2);
                    cg[mt][hl][3] = exp2p(cg[mt][hl][3] * SCL2);
                    lsum[mt][0] += cg[mt][hl][0] + cg[mt][hl][1];
                    lsum[mt][1] += cg[mt][hl][2] + cg[mt][hl][3];
                }
                float src[8] = {cg[mt][0][0], cg[mt][0][1], cg[mt][0][2], cg[mt][0][3],
                                cg[mt][1][0], cg[mt][1][1], cg[mt][1][2], cg[mt][1][3]};
                float ph[8], pl[8];
#pragma unroll
                for (int e = 0; e < 8; e++) {
                    __nv_bfloat16 hb = __float2bfloat16(src[e]);
                    ph[e] = __bfloat162float(hb);
                    pl[e] = src[e] - ph[e];
                }
#pragma unroll
                for (int q = 0; q < 4; q++) {
                    __nv_bfloat162 t0 = __floats2bfloat162_rn(ph[2*q], ph[2*q+1]);
                    __nv_bfloat162 t1 = __floats2bfloat162_rn(pl[2*q], pl[2*q+1]);
                    pfh[mt][q] = *(uint32_t*)&t0;
                    pfl[mt][q] = *(uint32_t*)&t1;
                }
            }

            // ---- PV(g) for both mt: each V fragment feeds 12 MMAs -----------
#pragma unroll
            for (int np = 0; np < 4; np++) {
                uint32_t vfh[4], vfl[4];
                const uint32_t vr = np * 16 + b_r;
                const uint32_t gv = (g * 2 + b_g0) ^ (vr & 7);
                const uint32_t voff = vr * 128 + gv * 16;
                ldsm_x4(vfh, sVh + voff);
                ldsm_x4(vfl, sVl + voff);
#pragma unroll
                for (int mt = 0; mt < 2; mt++) {
                    mma_bf16(o[mt][2*np],   pfh[mt], vfh);        // hh
                    mma_bf16(o[mt][2*np+1], pfh[mt], vfh + 2);
                    mma_bf16(o[mt][2*np],   pfh[mt], vfl);        // hl
                    mma_bf16(o[mt][2*np+1], pfh[mt], vfl + 2);
                    mma_bf16(o[mt][2*np],   pfl[mt], vfh);        // lh
                    mma_bf16(o[mt][2*np+1], pfl[mt], vfh + 2);
                }
            }
        }

        if (lid == 0) MBARRIER_ARRIVE(mbE + st * 8);
        if (tid == 0 && t + 3 < NKV) {
            MBARRIER_WAIT_PARITY(mbE + st * 8, (t / 3) & 1);
            issue(t + 3);
        }
    }

    // ---- row-sum reductions (once) ------------------------------------------
#pragma unroll
    for (int mt = 0; mt < 2; mt++) {
        lsum[mt][0] += __shfl_xor_sync(0xffffffffu, lsum[mt][0], 1);
        lsum[mt][0] += __shfl_xor_sync(0xffffffffu, lsum[mt][0], 2);
        lsum[mt][1] += __shfl_xor_sync(0xffffffffu, lsum[mt][1], 1);
        lsum[mt][1] += __shfl_xor_sync(0xffffffffu, lsum[mt][1], 2);
    }

    // ---- epilogue: normalize, write bf16 hi/lo into BLOCKED A staging ------
    const int b = bh >> 4;
    const int h = bh & 15;
#pragma unroll
    for (int mt = 0; mt < 2; mt++) {
        const float li0 = 1.f / lsum[mt][0];
        const float li1 = 1.f / lsum[mt][1];
        const int r0 = q0 + wid * 32 + mt * 16 + (lid >> 2);
        const int r1 = r0 + 8;
        const int grow0 = b * S_ + r0;
        const int grow1 = b * S_ + r1;

#pragma unroll
        for (int nt = 0; nt < 8; nt++) {
            const int col = h * 64 + nt * 8 + (lid & 3) * 2;
            float v0 = o[mt][nt][0] * li0, v1 = o[mt][nt][1] * li0;
            float v2 = o[mt][nt][2] * li1, v3 = o[mt][nt][3] * li1;
            __nv_bfloat16 h0,lo0,h1,lo1,h2,lo2,h3,lo3;
            split_bf16(v0,h0,lo0); split_bf16(v1,h1,lo1);
            split_bf16(v2,h2,lo2); split_bf16(v3,h3,lo3);
            const size_t o0 = ablk_off(grow0, col);
            const size_t o1 = ablk_off(grow1, col);
            *(__nv_bfloat162*)((char*)g_xh + o0) = __halves2bfloat162(h0, h1);
            *(__nv_bfloat162*)((char*)g_xl + o0) = __halves2bfloat162(lo0, lo1);
            *(__nv_bfloat162*)((char*)g_xh + o1) = __halves2bfloat162(h2, h3);
            *(__nv_bfloat162*)((char*)g_xl + o1) = __halves2bfloat162(lo2, lo3);
        }
    }
}

// ---------------------------------------------------------------------------
// Entry point
// ---------------------------------------------------------------------------
extern "C" void kernel_launch(void* const* d_in, const int* in_sizes, int n_in,
                              void* d_out, int out_size)
{
    const float* x  = (const float*)d_in[0];
    const float* Wq = (const float*)d_in[1];
    const float* bq = (const float*)d_in[2];
    const float* Wk = (const float*)d_in[3];
    const float* bk = (const float*)d_in[4];
    const float* Wv = (const float*)d_in[5];
    const float* bv = (const float*)d_in[6];
    const float* Wo = (const float*)d_in[7];
    const float* bo = (const float*)d_in[8];
    float* out = (float*)d_out;

    cudaFuncSetAttribute(gemm_mma_kernel,
                         cudaFuncAttributeMaxDynamicSharedMemorySize, GEMM_SMEM);
    cudaFuncSetAttribute(flash_mma_kernel,
                         cudaFuncAttributeMaxDynamicSharedMemorySize, FLASH_SMEM);

    convert_all_kernel<<<8192, 256>>>(x, Wq, Wk, Wv, Wo);
    gemm_mma_kernel<<<dim3(24, 32), 256, GEMM_SMEM>>>(bq, bk, bv, nullptr, 0);
    flash_mma_kernel<<<dim3(S_ / 128, B_ * H_), 128, FLASH_SMEM>>>();
    gemm_mma_kernel<<<dim3(8, 32), 256, GEMM_SMEM>>>(bo, bo, bo, out, 3072);
}

// round 16
// speedup vs baseline: 1.0227x; 1.0227x over previous
#include <cuda_runtime.h>
#include <cuda_bf16.h>
#include <math.h>
#include <cstdint>

// Problem constants
constexpr int B_  = 2;
constexpr int S_  = 2048;
constexpr int D_  = 1024;
constexpr int H_  = 16;
constexpr int HD_ = 64;
constexpr int M_  = B_ * S_;       // 4096

// Scratch (device globals). Blocked layouts for single-bulk 8 KB tiles.
__device__ __nv_bfloat16 g_xh[M_ * D_];
__device__ __nv_bfloat16 g_xl[M_ * D_];
__device__ __nv_bfloat16 g_wh[4 * D_ * D_];
__device__ __nv_bfloat16 g_wl[4 * D_ * D_];
__device__ __nv_bfloat16 g_Qh[B_ * H_ * S_ * HD_];   // Q LINEAR [b,h,s,hd]
__device__ __nv_bfloat16 g_Ql[B_ * H_ * S_ * HD_];
__device__ __nv_bfloat16 g_Kh[B_ * H_ * S_ * HD_];   // K blocked
__device__ __nv_bfloat16 g_Kl[B_ * H_ * S_ * HD_];
__device__ __nv_bfloat16 g_Vth[B_ * H_ * HD_ * S_];  // V^T blocked
__device__ __nv_bfloat16 g_Vtl[B_ * H_ * HD_ * S_];

// ---------------------------------------------------------------------------
// Blocked-layout byte offsets
// ---------------------------------------------------------------------------
__device__ __forceinline__ size_t ablk_off(int row, int col) {
    const int r = row & 127;
    const int g = ((col >> 3) & 3) ^ ((r >> 1) & 3);
    return (((size_t)(row >> 7) * 32 + (col >> 5)) << 13) + r * 64 + g * 16 + (col & 7) * 2;
}
__device__ __forceinline__ size_t kblk_off(int bh, int s, int hd) {
    const int r = s & 63;
    const int g = (hd >> 3) ^ (r & 7);
    return (((size_t)bh * 32 + (s >> 6)) << 13) + r * 128 + g * 16 + (hd & 7) * 2;
}
__device__ __forceinline__ size_t vblk_off(int bh, int s, int hd) {
    const int r = hd;
    const int c = s & 63;
    const int g = (c >> 3) ^ (r & 7);
    return (((size_t)bh * 32 + (s >> 6)) << 13) + r * 128 + g * 16 + (c & 7) * 2;
}

// ---------------------------------------------------------------------------
// PTX helpers
// ---------------------------------------------------------------------------
__device__ __forceinline__ uint32_t smem_to_u32(const void* p) {
    uint32_t a;
    asm("{ .reg .u64 t; cvta.to.shared.u64 t, %1; cvt.u32.u64 %0, t; }"
        : "=r"(a) : "l"(p));
    return a;
}

__device__ __forceinline__ void ldsm_x4(uint32_t* r, uint32_t addr) {
    asm volatile("ldmatrix.sync.aligned.m8n8.x4.shared.b16 {%0,%1,%2,%3}, [%4];"
        : "=r"(r[0]), "=r"(r[1]), "=r"(r[2]), "=r"(r[3]) : "r"(addr));
}

__device__ __forceinline__ void mma_bf16(float* c, const uint32_t* a, const uint32_t* b) {
    asm volatile(
        "mma.sync.aligned.m16n8k16.row.col.f32.bf16.bf16.f32 "
        "{%0,%1,%2,%3}, {%4,%5,%6,%7}, {%8,%9}, {%0,%1,%2,%3};"
        : "+f"(c[0]), "+f"(c[1]), "+f"(c[2]), "+f"(c[3])
        : "r"(a[0]), "r"(a[1]), "r"(a[2]), "r"(a[3]),
          "r"(b[0]), "r"(b[1]));
}

#define MBARRIER_INIT(mbar, count) \
    asm volatile("mbarrier.init.shared.b64 [%0], %1;" \
        :: "r"((uint32_t)(mbar)), "r"((uint32_t)(count)) : "memory")

#define MBARRIER_ARRIVE(mbar) \
    asm volatile("mbarrier.arrive.shared.b64 _, [%0];" \
        :: "r"((uint32_t)(mbar)) : "memory")

#define MBARRIER_EXPECT_TX(mbar, tx_bytes) \
    asm volatile("mbarrier.arrive.expect_tx.shared.b64 _, [%0], %1;" \
        :: "r"((uint32_t)(mbar)), "r"((uint32_t)(tx_bytes)) : "memory")

#define MBARRIER_WAIT_PARITY(mbar_smem_addr, phase_parity) do { \
    uint32_t _mbar = (uint32_t)(mbar_smem_addr); \
    uint32_t _parity = (uint32_t)(phase_parity); \
    uint32_t _done; \
    asm volatile( \
        "{\n\t.reg .pred p;\n\t" \
        "mbarrier.try_wait.parity.acquire.cta.shared::cta.b64 p, [%1], %2;\n\t" \
        "selp.b32 %0, 1, 0, p;\n\t}" \
        : "=r"(_done) : "r"(_mbar), "r"(_parity) : "memory"); \
    if (!_done) { \
        asm volatile( \
            "{\n\t.reg .pred P1;\n\t" \
            "WAIT_LOOP_%=:\n\t" \
            "mbarrier.try_wait.parity.acquire.cta.shared::cta.b64 P1, [%0], %1, 0x989680;\n\t" \
            "@P1 bra.uni WAIT_DONE_%=;\n\t" \
            "bra.uni WAIT_LOOP_%=;\n\t" \
            "WAIT_DONE_%=:\n\t}" \
            :: "r"(_mbar), "r"(_parity) : "memory"); \
    } \
} while(0)

#define CP_BULK(dst, src, bytes, mbar) \
    asm volatile("cp.async.bulk.shared::cta.global.mbarrier::complete_tx::bytes [%0], [%1], %2, [%3];" \
        :: "r"((uint32_t)(dst)), "l"(src), "r"((uint32_t)(bytes)), "r"((uint32_t)(mbar)) : "memory")

// FMA-pipe exp2 (avoids the MUFU ceiling).
__device__ __forceinline__ float exp2p(float x) {
    x = fmaxf(x, -28.0f);
    float n = floorf(x);
    float f = x - n;
    float p = 1.54035304e-4f;
    p = fmaf(p, f, 1.33335581e-3f);
    p = fmaf(p, f, 9.61812911e-3f);
    p = fmaf(p, f, 5.55041087e-2f);
    p = fmaf(p, f, 2.40226507e-1f);
    p = fmaf(p, f, 6.93147181e-1f);
    p = fmaf(p, f, 1.0f);
    return __int_as_float(__float_as_int(p) + (((int)n) << 23));
}

__device__ __forceinline__ void split_bf16(float v, __nv_bfloat16& h, __nv_bfloat16& l) {
    h = __float2bfloat16(v);
    l = __float2bfloat16(v - __bfloat162float(h));
}

// ---------------------------------------------------------------------------
// One-shot converter: x -> g_xh/g_xl (blocked) ; Wq..Wo -> g_wh/g_wl (blocked)
// ---------------------------------------------------------------------------
__global__ void __launch_bounds__(256)
convert_all_kernel(const float* __restrict__ x,
                   const float* __restrict__ Wq, const float* __restrict__ Wk,
                   const float* __restrict__ Wv, const float* __restrict__ Wo)
{
    const int tid = threadIdx.x;
    const int blk = blockIdx.x;

    const float* src;
    __nv_bfloat16 *hi, *lo;
    int row;
    if (blk < 4096) {
        src = x + (size_t)blk * 1024; hi = g_xh; lo = g_xl; row = blk;
    } else {
        const int t = blk - 4096;
        const int w = t >> 10;
        const int lb = t & 1023;
        src = ((w == 0) ? Wq : (w == 1) ? Wk : (w == 2) ? Wv : Wo) + (size_t)lb * 1024;
        hi = g_wh; lo = g_wl; row = w * 1024 + lb;
    }

    const int col = tid * 4;
    float4 v = *(const float4*)(src + col);
    float f[4] = {v.x, v.y, v.z, v.w};
    __nv_bfloat16 h[4], l[4];
#pragma unroll
    for (int k = 0; k < 4; k++) split_bf16(f[k], h[k], l[k]);

    const size_t off = ablk_off(row, col);
    *(__nv_bfloat162*)((char*)hi + off)     = __halves2bfloat162(h[0], h[1]);
    *(__nv_bfloat162*)((char*)hi + off + 4) = __halves2bfloat162(h[2], h[3]);
    *(__nv_bfloat162*)((char*)lo + off)     = __halves2bfloat162(l[0], l[1]);
    *(__nv_bfloat162*)((char*)lo + off + 4) = __halves2bfloat162(l[2], l[3]);
}

// ---------------------------------------------------------------------------
// bf16x3 GEMM via mma.sync + TMA-bulk staging, warp-decoupled pipeline
// (unchanged from round 14, known-good).
// ---------------------------------------------------------------------------
constexpr int GSTAGE    = 32768;
constexpr int GEMM_SMEM = 3 * GSTAGE;

__global__ void __launch_bounds__(256, 2)
gemm_mma_kernel(const float* __restrict__ b0,
                const float* __restrict__ b1,
                const float* __restrict__ b2,
                float* __restrict__ dst,
                int wrow0)
{
    extern __shared__ __align__(1024) char smem[];
    __shared__ __align__(8) uint64_t mbar_st[6];      // full[3], empty[3]
    const uint32_t sb  = smem_to_u32(smem);
    const uint32_t mbF = smem_to_u32(&mbar_st[0]);
    const uint32_t mbE = smem_to_u32(&mbar_st[3]);
    const int tid = threadIdx.x;
    const int wid = tid >> 5;
    const int lid = tid & 31;
    const int wm  = wid & 3;
    const int wn  = wid >> 2;
    const int bm  = blockIdx.y * 128;
    const int bn  = blockIdx.x * 128;
    const int sel = bn >> 10;

    const float* bias = dst ? b0 : (sel == 0 ? b0 : sel == 1 ? b1 : b2);
    const int wt = (wrow0 + bn) >> 7;

    if (tid == 0) {
#pragma unroll
        for (int i = 0; i < 3; i++) {
            MBARRIER_INIT(mbF + i * 8, 1);
            MBARRIER_INIT(mbE + i * 8, 8);
        }
    }
    __syncthreads();

    auto issue = [&](int st) {
        const int b = st % 3;
        const uint32_t d  = sb + b * GSTAGE;
        const uint32_t mb = mbF + b * 8;
        MBARRIER_EXPECT_TX(mb, 32768);
        const size_t at = (((size_t)blockIdx.y * 32 + st) << 13);
        const size_t bt = (((size_t)wt * 32 + st) << 13);
        CP_BULK(d,         (const char*)g_xh + at, 8192, mb);
        CP_BULK(d + 8192,  (const char*)g_xl + at, 8192, mb);
        CP_BULK(d + 16384, (const char*)g_wh + bt, 8192, mb);
        CP_BULK(d + 24576, (const char*)g_wl + bt, 8192, mb);
    };
    if (tid == 0) { issue(0); issue(1); issue(2); }

    float c[2][8][4];
#pragma unroll
    for (int i = 0; i < 2; i++)
#pragma unroll
        for (int j = 0; j < 8; j++)
#pragma unroll
            for (int k = 0; k < 4; k++) c[i][j][k] = 0.f;

    const uint32_t a_r  = lid & 15;
    const uint32_t a_g0 = (lid >> 4) & 1;
    const uint32_t b_r  = ((lid >> 4) * 8) + (lid & 7);
    const uint32_t b_g0 = (lid >> 3) & 1;

    const int NCH = D_ / 32;
    for (int ch = 0; ch < NCH; ch++) {
        const int st = ch % 3;
        MBARRIER_WAIT_PARITY(mbF + st * 8, (ch / 3) & 1);

        const uint32_t sA_h = sb + st * GSTAGE;
        const uint32_t sA_l = sA_h + 8192;
        const uint32_t sB_h = sA_h + 16384;
        const uint32_t sB_l = sA_h + 24576;

        auto boff_of = [&](int kk, int np) -> uint32_t {
            const uint32_t br = wn * 64 + np * 16 + b_r;
            const uint32_t gb = (kk * 2 + b_g0) ^ ((br >> 1) & 3);
            return br * 64 + gb * 16;
        };

#pragma unroll
        for (int kk = 0; kk < 2; kk++) {
            uint32_t ah[2][4], al[2][4];
#pragma unroll
            for (int mt = 0; mt < 2; mt++) {
                const uint32_t ar = wm * 32 + mt * 16 + a_r;
                const uint32_t ga = (kk * 2 + a_g0) ^ ((ar >> 1) & 3);
                const uint32_t aoff = ar * 64 + ga * 16;
                ldsm_x4(ah[mt], sA_h + aoff);
                ldsm_x4(al[mt], sA_l + aoff);
            }
            uint32_t bh[2][4], bl[2][4];
            {
                const uint32_t o0 = boff_of(kk, 0);
                ldsm_x4(bh[0], sB_h + o0);
                ldsm_x4(bl[0], sB_l + o0);
            }
#pragma unroll
            for (int np = 0; np < 4; np++) {
                const int cur = np & 1;
                if (np < 3) {
                    const uint32_t on = boff_of(kk, np + 1);
                    ldsm_x4(bh[cur ^ 1], sB_h + on);
                    ldsm_x4(bl[cur ^ 1], sB_l + on);
                }
#pragma unroll
                for (int mt = 0; mt < 2; mt++) {
                    mma_bf16(c[mt][2*np],   ah[mt], bh[cur]);       // hh
                    mma_bf16(c[mt][2*np+1], ah[mt], bh[cur] + 2);
                    mma_bf16(c[mt][2*np],   ah[mt], bl[cur]);       // hl
                    mma_bf16(c[mt][2*np+1], ah[mt], bl[cur] + 2);
                    mma_bf16(c[mt][2*np],   al[mt], bh[cur]);       // lh
                    mma_bf16(c[mt][2*np+1], al[mt], bh[cur] + 2);
                }
            }
        }

        if (lid == 0) MBARRIER_ARRIVE(mbE + st * 8);
        if (tid == 0 && ch + 3 < NCH) {
            MBARRIER_WAIT_PARITY(mbE + st * 8, (ch / 3) & 1);
            issue(ch + 3);
        }
    }

    // ---- epilogue ------------------------------------------------------
#pragma unroll
    for (int mt = 0; mt < 2; mt++) {
#pragma unroll
        for (int nt = 0; nt < 8; nt++) {
            const int row0 = bm + wm * 32 + mt * 16 + (lid >> 2);
            const int row1 = row0 + 8;
            const int col  = bn + wn * 64 + nt * 8 + (lid & 3) * 2;
            const int colw = col & 1023;
            const float bx = __ldg(bias + colw);
            const float by = __ldg(bias + colw + 1);
            float v0 = c[mt][nt][0] + bx, v1 = c[mt][nt][1] + by;
            float v2 = c[mt][nt][2] + bx, v3 = c[mt][nt][3] + by;

            if (dst) {
                *(float2*)(dst + (size_t)row0 * D_ + col) = make_float2(v0, v1);
                *(float2*)(dst + (size_t)row1 * D_ + col) = make_float2(v2, v3);
            } else {
                const int h  = colw >> 6;
                const int hd = colw & 63;
                const int bb0 = row0 >> 11, ss0 = row0 & (S_ - 1);
                const int bb1 = row1 >> 11, ss1 = row1 & (S_ - 1);
                const int bhi0 = bb0 * H_ + h, bhi1 = bb1 * H_ + h;
                __nv_bfloat16 h0,l0,h1,l1,h2,l2,h3,l3;
                split_bf16(v0,h0,l0); split_bf16(v1,h1,l1);
                split_bf16(v2,h2,l2); split_bf16(v3,h3,l3);
                if (sel == 2) {
                    *(__nv_bfloat16*)((char*)g_Vth + vblk_off(bhi0, ss0, hd))     = h0;
                    *(__nv_bfloat16*)((char*)g_Vtl + vblk_off(bhi0, ss0, hd))     = l0;
                    *(__nv_bfloat16*)((char*)g_Vth + vblk_off(bhi0, ss0, hd + 1)) = h1;
                    *(__nv_bfloat16*)((char*)g_Vtl + vblk_off(bhi0, ss0, hd + 1)) = l1;
                    *(__nv_bfloat16*)((char*)g_Vth + vblk_off(bhi1, ss1, hd))     = h2;
                    *(__nv_bfloat16*)((char*)g_Vtl + vblk_off(bhi1, ss1, hd))     = l2;
                    *(__nv_bfloat16*)((char*)g_Vth + vblk_off(bhi1, ss1, hd + 1)) = h3;
                    *(__nv_bfloat16*)((char*)g_Vtl + vblk_off(bhi1, ss1, hd + 1)) = l3;
                } else if (sel == 1) {
                    const size_t o0 = kblk_off(bhi0, ss0, hd);
                    const size_t o1 = kblk_off(bhi1, ss1, hd);
                    *(__nv_bfloat162*)((char*)g_Kh + o0) = __halves2bfloat162(h0, h1);
                    *(__nv_bfloat162*)((char*)g_Kl + o0) = __halves2bfloat162(l0, l1);
                    *(__nv_bfloat162*)((char*)g_Kh + o1) = __halves2bfloat162(h2, h3);
                    *(__nv_bfloat162*)((char*)g_Kl + o1) = __halves2bfloat162(l2, l3);
                } else {
                    size_t i0 = (((size_t)bhi0 * S_) + ss0) * HD_ + hd;
                    size_t i1 = (((size_t)bhi1 * S_) + ss1) * HD_ + hd;
                    *(__nv_bfloat162*)(g_Qh + i0) = __halves2bfloat162(h0, h1);
                    *(__nv_bfloat162*)(g_Ql + i0) = __halves2bfloat162(l0, l1);
                    *(__nv_bfloat162*)(g_Qh + i1) = __halves2bfloat162(h2, h3);
                    *(__nv_bfloat162*)(g_Ql + i1) = __halves2bfloat162(l2, l3);
                }
            }
        }
    }
}

// ---------------------------------------------------------------------------
// Flash attention (round-14 8-warp structure) with PRMT truncation-split
// P-pack: hi = top-16-bits (1 PRMT per pair, ALU pipe), lo = RN(p - hi).
// FMA-pipe ops in pack halve; error 2^-15 representation (vs 2^-16) -> safe.
// ---------------------------------------------------------------------------
constexpr int FSTAGE     = 32768;
constexpr int FLASH_SMEM = 3 * FSTAGE;
constexpr float SCL2 = 0.18033688f;            // 0.125 * log2(e)

__global__ void __launch_bounds__(256, 2)
flash_mma_kernel()
{
    extern __shared__ __align__(1024) char fsm[];
    __shared__ __align__(8) uint64_t fmbar_st[6];     // full[3], empty[3]
    const uint32_t sb  = smem_to_u32(fsm);
    const uint32_t mbF = smem_to_u32(&fmbar_st[0]);
    const uint32_t mbE = smem_to_u32(&fmbar_st[3]);
    const int tid = threadIdx.x;
    const int wid = tid >> 5;
    const int lid = tid & 31;
    const int bh  = blockIdx.y;
    const int q0  = blockIdx.x * 128;

    const size_t qk_base = (size_t)bh * S_ * HD_;
    const __nv_bfloat16* Qh = g_Qh + qk_base;
    const __nv_bfloat16* Ql = g_Ql + qk_base;
    const char* Khb = (const char*)g_Kh + ((size_t)bh * 32 << 13);
    const char* Klb = (const char*)g_Kl + ((size_t)bh * 32 << 13);
    const char* Vhb = (const char*)g_Vth + ((size_t)bh * 32 << 13);
    const char* Vlb = (const char*)g_Vtl + ((size_t)bh * 32 << 13);

    if (tid == 0) {
#pragma unroll
        for (int i = 0; i < 3; i++) {
            MBARRIER_INIT(mbF + i * 8, 1);
            MBARRIER_INIT(mbE + i * 8, 8);
        }
    }
    __syncthreads();

    auto issue = [&](int t) {
        const int b = t % 3;
        const uint32_t d  = sb + b * FSTAGE;
        const uint32_t mb = mbF + b * 8;
        MBARRIER_EXPECT_TX(mb, 32768);
        const size_t toff = ((size_t)t << 13);
        CP_BULK(d,         Khb + toff, 8192, mb);
        CP_BULK(d + 8192,  Klb + toff, 8192, mb);
        CP_BULK(d + 16384, Vhb + toff, 8192, mb);
        CP_BULK(d + 24576, Vlb + toff, 8192, mb);
    };
    if (tid == 0) { issue(0); issue(1); issue(2); }

    // Q fragments straight from gmem
    uint32_t qfh[4][4], qfl[4][4];
    {
        const int g  = lid >> 2;
        const int tq = lid & 3;
        const int row0 = q0 + wid * 16 + g;
#pragma unroll
        for (int kk = 0; kk < 4; kk++) {
            const int c0 = kk * 16 + 2 * tq;
            const size_t i00 = (size_t)row0 * HD_ + c0;
            const size_t i10 = i00 + 8 * HD_;
            qfh[kk][0] = *(const uint32_t*)(Qh + i00);
            qfh[kk][1] = *(const uint32_t*)(Qh + i10);
            qfh[kk][2] = *(const uint32_t*)(Qh + i00 + 8);
            qfh[kk][3] = *(const uint32_t*)(Qh + i10 + 8);
            qfl[kk][0] = *(const uint32_t*)(Ql + i00);
            qfl[kk][1] = *(const uint32_t*)(Ql + i10);
            qfl[kk][2] = *(const uint32_t*)(Ql + i00 + 8);
            qfl[kk][3] = *(const uint32_t*)(Ql + i10 + 8);
        }
    }

    const uint32_t b_r  = ((lid >> 4) * 8) + (lid & 7);
    const uint32_t b_g0 = (lid >> 3) & 1;

    float o[8][4];
#pragma unroll
    for (int i = 0; i < 8; i++)
#pragma unroll
        for (int j = 0; j < 4; j++) o[i][j] = 0.f;
    float l0 = 0.f, l1 = 0.f;

    const int NKV = S_ / 64;
    for (int t = 0; t < NKV; t++) {
        const int st = t % 3;
        MBARRIER_WAIT_PARITY(mbF + st * 8, (t / 3) & 1);

        const uint32_t sKh = sb + st * FSTAGE;
        const uint32_t sKl = sKh + 8192;
        const uint32_t sVh = sKh + 16384;
        const uint32_t sVl = sKh + 24576;

        auto koff_of = [&](int g, int kk) -> uint32_t {
            const uint32_t kr = g * 16 + b_r;
            const uint32_t gk = (kk * 2 + b_g0) ^ (kr & 7);
            return kr * 128 + gk * 16;
        };
        auto voff_of = [&](int g, int np) -> uint32_t {
            const uint32_t vr = np * 16 + b_r;
            const uint32_t gv = (g * 2 + b_g0) ^ (vr & 7);
            return vr * 128 + gv * 16;
        };

        auto qk_group = [&](int g, float cg[2][4]) {
#pragma unroll
            for (int j = 0; j < 4; j++) { cg[0][j] = 0.f; cg[1][j] = 0.f; }
            uint32_t kfh[2][4], kfl[2][4];
            {
                const uint32_t o0 = koff_of(g, 0);
                ldsm_x4(kfh[0], sKh + o0);
                ldsm_x4(kfl[0], sKl + o0);
            }
#pragma unroll
            for (int kk = 0; kk < 4; kk++) {
                const int cur = kk & 1;
                if (kk < 3) {
                    const uint32_t on = koff_of(g, kk + 1);
                    ldsm_x4(kfh[cur ^ 1], sKh + on);
                    ldsm_x4(kfl[cur ^ 1], sKl + on);
                }
                mma_bf16(cg[0], qfh[kk], kfh[cur]);           // hh
                mma_bf16(cg[1], qfh[kk], kfh[cur] + 2);
                mma_bf16(cg[0], qfh[kk], kfl[cur]);           // hl
                mma_bf16(cg[1], qfh[kk], kfl[cur] + 2);
                mma_bf16(cg[0], qfl[kk], kfh[cur]);           // lh
                mma_bf16(cg[1], qfl[kk], kfh[cur] + 2);
            }
        };

        float cgbuf[2][2][4];
        qk_group(0, cgbuf[0]);

#pragma unroll
        for (int g = 0; g < 4; g++) {
            float (*cg)[4] = cgbuf[g & 1];

#pragma unroll
            for (int hl = 0; hl < 2; hl++) {
                cg[hl][0] = exp2p(cg[hl][0] * SCL2);
                cg[hl][1] = exp2p(cg[hl][1] * SCL2);
                cg[hl][2] = exp2p(cg[hl][2] * SCL2);
                cg[hl][3] = exp2p(cg[hl][3] * SCL2);
                l0 += cg[hl][0] + cg[hl][1];
                l1 += cg[hl][2] + cg[hl][3];
            }

            // ---- P-pack: PRMT truncation split -----------------------------
            uint32_t pfh[4], pfl[4];
            {
                float src[8] = {cg[0][0], cg[0][1], cg[0][2], cg[0][3],
                                cg[1][0], cg[1][1], cg[1][2], cg[1][3]};
#pragma unroll
                for (int q = 0; q < 4; q++) {
                    const uint32_t ua = __float_as_uint(src[2*q]);
                    const uint32_t ub = __float_as_uint(src[2*q+1]);
                    pfh[q] = __byte_perm(ua, ub, 0x7632);      // [a.hi16, b.hi16]
                    const float la = src[2*q]   - __uint_as_float(ua & 0xFFFF0000u);
                    const float lb = src[2*q+1] - __uint_as_float(ub & 0xFFFF0000u);
                    __nv_bfloat162 t1 = __floats2bfloat162_rn(la, lb);
                    pfl[q] = *(uint32_t*)&t1;
                }
            }

            if (g < 3) qk_group(g + 1, cgbuf[(g & 1) ^ 1]);

            uint32_t vfh[2][4], vfl[2][4];
            {
                const uint32_t o0 = voff_of(g, 0);
                ldsm_x4(vfh[0], sVh + o0);
                ldsm_x4(vfl[0], sVl + o0);
            }
#pragma unroll
            for (int np = 0; np < 4; np++) {
                const int cur = np & 1;
                if (np < 3) {
                    const uint32_t on = voff_of(g, np + 1);
                    ldsm_x4(vfh[cur ^ 1], sVh + on);
                    ldsm_x4(vfl[cur ^ 1], sVl + on);
                }
                mma_bf16(o[2*np],   pfh, vfh[cur]);           // hh
                mma_bf16(o[2*np+1], pfh, vfh[cur] + 2);
                mma_bf16(o[2*np],   pfh, vfl[cur]);           // hl
                mma_bf16(o[2*np+1], pfh, vfl[cur] + 2);
                mma_bf16(o[2*np],   pfl, vfh[cur]);           // lh
                mma_bf16(o[2*np+1], pfl, vfh[cur] + 2);
            }
        }

        if (lid == 0) MBARRIER_ARRIVE(mbE + st * 8);
        if (tid == 0 && t + 3 < NKV) {
            MBARRIER_WAIT_PARITY(mbE + st * 8, (t / 3) & 1);
            issue(t + 3);
        }
    }

    // ---- one-time row-sum reduction -----------------------------------------
    l0 += __shfl_xor_sync(0xffffffffu, l0, 1);
    l0 += __shfl_xor_sync(0xffffffffu, l0, 2);
    l1 += __shfl_xor_sync(0xffffffffu, l1, 1);
    l1 += __shfl_xor_sync(0xffffffffu, l1, 2);

    // ---- epilogue: normalize, write bf16 hi/lo into BLOCKED A staging ------
    const int b = bh >> 4;
    const int h = bh & 15;
    const float li0 = 1.f / l0;
    const float li1 = 1.f / l1;
    const int r0 = q0 + wid * 16 + (lid >> 2);
    const int r1 = r0 + 8;
    const int grow0 = b * S_ + r0;
    const int grow1 = b * S_ + r1;

#pragma unroll
    for (int nt = 0; nt < 8; nt++) {
        const int col = h * 64 + nt * 8 + (lid & 3) * 2;
        float v0 = o[nt][0] * li0, v1 = o[nt][1] * li0;
        float v2 = o[nt][2] * li1, v3 = o[nt][3] * li1;
        __nv_bfloat16 h0,lo0,h1,lo1,h2,lo2,h3,lo3;
        split_bf16(v0,h0,lo0); split_bf16(v1,h1,lo1);
        split_bf16(v2,h2,lo2); split_bf16(v3,h3,lo3);
        const size_t o0 = ablk_off(grow0, col);
        const size_t o1 = ablk_off(grow1, col);
        *(__nv_bfloat162*)((char*)g_xh + o0) = __halves2bfloat162(h0, h1);
        *(__nv_bfloat162*)((char*)g_xl + o0) = __halves2bfloat162(lo0, lo1);
        *(__nv_bfloat162*)((char*)g_xh + o1) = __halves2bfloat162(h2, h3);
        *(__nv_bfloat162*)((char*)g_xl + o1) = __halves2bfloat162(lo2, lo3);
    }
}

// ---------------------------------------------------------------------------
// Entry point
// ---------------------------------------------------------------------------
extern "C" void kernel_launch(void* const* d_in, const int* in_sizes, int n_in,
                              void* d_out, int out_size)
{
    const float* x  = (const float*)d_in[0];
    const float* Wq = (const float*)d_in[1];
    const float* bq = (const float*)d_in[2];
    const float* Wk = (const float*)d_in[3];
    const float* bk = (const float*)d_in[4];
    const float* Wv = (const float*)d_in[5];
    const float* bv = (const float*)d_in[6];
    const float* Wo = (const float*)d_in[7];
    const float* bo = (const float*)d_in[8];
    float* out = (float*)d_out;

    cudaFuncSetAttribute(gemm_mma_kernel,
                         cudaFuncAttributeMaxDynamicSharedMemorySize, GEMM_SMEM);
    cudaFuncSetAttribute(flash_mma_kernel,
                         cudaFuncAttributeMaxDynamicSharedMemorySize, FLASH_SMEM);

    convert_all_kernel<<<8192, 256>>>(x, Wq, Wk, Wv, Wo);
    gemm_mma_kernel<<<dim3(24, 32), 256, GEMM_SMEM>>>(bq, bk, bv, nullptr, 0);
    flash_mma_kernel<<<dim3(S_ / 128, B_ * H_), 256, FLASH_SMEM>>>();
    gemm_mma_kernel<<<dim3(8, 32), 256, GEMM_SMEM>>>(bo, bo, bo, out, 3072);
}